// round 13
// baseline (speedup 1.0000x reference)
#include <cuda_runtime.h>
#include <cuda_bf16.h>
#include <cuda_fp16.h>
#include <cstdint>

// ----------------------------------------------------------------------------
// AxialAttention (height axis). x(16,512,64,64), w_qkv(1024,512), relative(128,127)
// NW=1024 (b = n*64+w), G=8 heads, q/k: 32 ch, v: 64 ch per head.
// K1 (QKV 1x1-conv GEMM): bf16 hi/lo split on mma.sync (HMMA); tcgen05 is
// unavailable (harness targets compute_103, no 'a' feature set).
// This round: 4-stage single-barrier GEMM pipeline; P and sv stored fp16.
// ----------------------------------------------------------------------------

#define CIN 512
#define OC  1024
#define BN_EPS 1e-5f

// ------------------------------ scratch (__device__ globals; no allocations)
__device__ float g_bias[OC];                 // folded conv bias
__device__ float g_emb[128 * 64 * 64];       // all_emb[ch][i][j] = rel[ch, i-j+63]
__device__ float g_s[24];                    // bns scales (qk: g, qr: 8+g, kr: 16+g)
__device__ float g_oa[1024];                 // bno scales per filter (sv, sve)
__device__ float g_ob[512];                  // bno combined bias per filter
__device__ __nv_bfloat16 g_w_hi[OC * CIN];   // folded conv weight, bf16 hi
__device__ __nv_bfloat16 g_w_lo[OC * CIN];   // bf16 lo residual
__device__ __nv_bfloat16 g_xt_hi[(size_t)16 * 4096 * 512]; // x^T [n*4096+hw][c] hi
__device__ __nv_bfloat16 g_xt_lo[(size_t)16 * 4096 * 512]; // lo
__device__ float g_qkv[(size_t)16 * 1024 * 4096];   // [n][o][h*64+w]
__device__ float g_qkvT[(size_t)16 * 1024 * 4096];  // [n][o][w*64+h]
__device__ float g_sim[(size_t)1024 * 8 * 4096];    // [b][g][i][j]: qr
__device__ float g_simT[(size_t)1024 * 8 * 4096];   // [b][g][j][i]: kr
__device__ __half g_p[(size_t)1024 * 8 * 4096];     // [b][g][i][j]: softmax P (fp16)
__device__ __half g_svh[(size_t)16 * 8 * 64 * 4096];// [n][g][i][w*64+c] sv (fp16)

// ------------------------------------------------------------- PTX helpers
__device__ __forceinline__ float2 ffma2(float2 a, float2 b, float2 c) {
    float2 d;
    asm("{\n\t"
        ".reg .b64 ra, rb, rc;\n\t"
        "mov.b64 ra, {%2, %3};\n\t"
        "mov.b64 rb, {%4, %5};\n\t"
        "mov.b64 rc, {%6, %7};\n\t"
        "fma.rn.f32x2 rc, ra, rb, rc;\n\t"
        "mov.b64 {%0, %1}, rc;\n\t"
        "}"
        : "=f"(d.x), "=f"(d.y)
        : "f"(a.x), "f"(a.y), "f"(b.x), "f"(b.y), "f"(c.x), "f"(c.y));
    return d;
}

__device__ __forceinline__ uint32_t s2u(const void* p) {
    uint32_t a;
    asm("{ .reg .u64 t; cvta.to.shared.u64 t, %1; cvt.u32.u64 %0, t; }" : "=r"(a) : "l"(p));
    return a;
}
__device__ __forceinline__ void cp16(uint32_t s, const void* g) {
    asm volatile("cp.async.cg.shared.global [%0], [%1], 16;" :: "r"(s), "l"(g));
}
#define CP_COMMIT() asm volatile("cp.async.commit_group;" ::: "memory")
#define CP_WAIT(n)  asm volatile("cp.async.wait_group %0;" :: "n"(n) : "memory")

__device__ __forceinline__ void ldm4(uint32_t* r, uint32_t addr) {
    asm volatile("ldmatrix.sync.aligned.m8n8.x4.shared.b16 {%0,%1,%2,%3}, [%4];"
                 : "=r"(r[0]), "=r"(r[1]), "=r"(r[2]), "=r"(r[3]) : "r"(addr));
}
__device__ __forceinline__ void mma16816(float* c, const uint32_t* a, const uint32_t* b) {
    asm volatile(
        "mma.sync.aligned.m16n8k16.row.col.f32.bf16.bf16.f32 "
        "{%0,%1,%2,%3}, {%4,%5,%6,%7}, {%8,%9}, {%0,%1,%2,%3};"
        : "+f"(c[0]), "+f"(c[1]), "+f"(c[2]), "+f"(c[3])
        : "r"(a[0]), "r"(a[1]), "r"(a[2]), "r"(a[3]), "r"(b[0]), "r"(b[1]));
}

__device__ __forceinline__ uint32_t pack_h2(float a, float b) {
    __half2 h = __floats2half2_rn(a, b);
    return *(uint32_t*)&h;
}

// -------------------------------------------------------------- prep kernels
__global__ void k_conv_w(const float* __restrict__ w,
                         const float* __restrict__ gg, const float* __restrict__ gb,
                         const float* __restrict__ gm, const float* __restrict__ gv) {
    int o = blockIdx.x, c = threadIdx.x;
    float sc = gg[o] * rsqrtf(gv[o] + BN_EPS);
    float v = w[o * CIN + c] * sc;
    __nv_bfloat16 h = __float2bfloat16(v);
    g_w_hi[o * CIN + c] = h;
    g_w_lo[o * CIN + c] = __float2bfloat16(v - __bfloat162float(h));
    if (c == 0) g_bias[o] = gb[o] - gm[o] * sc;
}

__global__ void k_prep_emb(const float* __restrict__ rel) {
    int ch = blockIdx.x, i = blockIdx.y, j = threadIdx.x;
    g_emb[(ch * 64 + i) * 64 + j] = rel[ch * 127 + (i - j + 63)];
}

__global__ void k_prep_sc(const float* __restrict__ sg, const float* __restrict__ svv,
                          const float* __restrict__ og, const float* __restrict__ ob_,
                          const float* __restrict__ om, const float* __restrict__ ov) {
    int t = threadIdx.x;  // 512
    if (t < 24) g_s[t] = sg[t] * rsqrtf(svv[t] + BN_EPS);
    float a0 = og[2 * t] * rsqrtf(ov[2 * t] + BN_EPS);
    float a1 = og[2 * t + 1] * rsqrtf(ov[2 * t + 1] + BN_EPS);
    g_oa[2 * t] = a0;
    g_oa[2 * t + 1] = a1;
    g_ob[t] = (ob_[2 * t] - om[2 * t] * a0) + (ob_[2 * t + 1] - om[2 * t + 1] * a1);
}

// x [n][c][hw] fp32 -> x^T [n*4096+hw][c] bf16 hi/lo (K-contiguous B for mma)
__global__ void __launch_bounds__(256) k_conv_x(const float* __restrict__ x) {
    const int hw0 = blockIdx.x * 64, c0 = blockIdx.y * 64, n = blockIdx.z;
    __shared__ float sm[64 * 65];
    const int tid = threadIdx.x;
    const float* src = x + ((size_t)n * CIN + c0) * 4096 + hw0;
#pragma unroll
    for (int l = 0; l < 16; l++) {
        int idx = tid + l * 256;
        int r = idx >> 6, u = idx & 63;  // r = c-local, u = hw-local
        sm[r * 65 + u] = src[(size_t)r * 4096 + u];
    }
    __syncthreads();
    __nv_bfloat16* dh = g_xt_hi + ((size_t)n * 4096 + hw0) * CIN + c0;
    __nv_bfloat16* dl = g_xt_lo + ((size_t)n * 4096 + hw0) * CIN + c0;
#pragma unroll
    for (int l = 0; l < 16; l++) {
        int idx = tid + l * 256;
        int r = idx >> 6, u = idx & 63;  // r = hw-local, u = c-local
        float v = sm[u * 65 + r];
        __nv_bfloat16 h = __float2bfloat16(v);
        dh[(size_t)r * CIN + u] = h;
        dl[(size_t)r * CIN + u] = __float2bfloat16(v - __bfloat162float(h));
    }
}

// ------------------------------------------ K1: bf16-split mma.sync GEMM
// per n: qkv[o0+128, col0+128] = W(1024x512) @ X(512x4096) + bias
// CTA 128x128, BK=32, 4-stage cp.async ring (one barrier per chunk).
// Warp tile 64x32 (2x4 warp grid). SMEM row stride 80B (conflict-free ldmatrix).
#define AROWB   80
#define MATB    (128 * AROWB)     // 10240 per matrix
#define STAGEB  (4 * MATB)        // A_hi, A_lo, B_hi, B_lo = 40960
#define NSTAGE  4
#define SMEM_GEMM (NSTAGE * STAGEB)  // 163840

__device__ __forceinline__ void gemm_loads(int tid, int o0, size_t nb, int k0, uint32_t s) {
#pragma unroll
    for (int l = 0; l < 2; l++) {
        int idx = tid + l * 256;           // 0..511
        int r = idx >> 2, t = idx & 3;     // row, 16B chunk
        uint32_t so = r * AROWB + t * 16;
        size_t ga = (size_t)(o0 + r) * CIN + k0 + t * 8;
        cp16(s + so, g_w_hi + ga);
        cp16(s + MATB + so, g_w_lo + ga);
        size_t gb = (nb + r) * CIN + k0 + t * 8;
        cp16(s + 2 * MATB + so, g_xt_hi + gb);
        cp16(s + 3 * MATB + so, g_xt_lo + gb);
    }
}

__global__ void __launch_bounds__(256) k_gemm() {
    extern __shared__ __align__(128) char smem[];
    const uint32_t sb = s2u(smem);
    const int tid = threadIdx.x, wid = tid >> 5, lane = tid & 31;
    const int col0 = blockIdx.x * 128;
    const int o0 = blockIdx.y * 128;
    const int n = blockIdx.z;
    const size_t nb = (size_t)n * 4096 + col0;
    const int wm = (wid >> 2) * 64, wn = (wid & 3) * 32;

    float acc[4][4][4];
#pragma unroll
    for (int mi = 0; mi < 4; mi++)
#pragma unroll
        for (int ni = 0; ni < 4; ni++)
#pragma unroll
            for (int e = 0; e < 4; e++) acc[mi][ni][e] = 0.f;

    // prologue: stages 0..2 in flight
    gemm_loads(tid, o0, nb, 0, sb);
    CP_COMMIT();
    gemm_loads(tid, o0, nb, 32, sb + STAGEB);
    CP_COMMIT();
    gemm_loads(tid, o0, nb, 64, sb + 2 * STAGEB);
    CP_COMMIT();

    const int lrow = lane & 15;
    const int lchk = (lane >> 4) * 16;

    for (int c = 0; c < 16; c++) {
        if (c < 14) CP_WAIT(2);
        else if (c == 14) CP_WAIT(1);
        else CP_WAIT(0);
        __syncthreads();   // stage c visible; stage (c+3)&3 fully consumed
        if (c + 3 < 16) {
            gemm_loads(tid, o0, nb, (c + 3) * 32, sb + ((c + 3) & 3) * STAGEB);
            CP_COMMIT();
        }
        const uint32_t stg = sb + (c & 3) * STAGEB;
#pragma unroll
        for (int ks = 0; ks < 2; ks++) {
            const int ksb = ks * 32;
            uint32_t ah[4][4], bh[4][2], bl[4][2];
#pragma unroll
            for (int mi = 0; mi < 4; mi++)
                ldm4(ah[mi], stg + (wm + mi * 16 + lrow) * AROWB + ksb + lchk);
#pragma unroll
            for (int nj = 0; nj < 2; nj++) {
                uint32_t r[4];
                ldm4(r, stg + 2 * MATB + (wn + nj * 16 + lrow) * AROWB + ksb + lchk);
                bh[2 * nj][0] = r[0]; bh[2 * nj][1] = r[2];
                bh[2 * nj + 1][0] = r[1]; bh[2 * nj + 1][1] = r[3];
                ldm4(r, stg + 3 * MATB + (wn + nj * 16 + lrow) * AROWB + ksb + lchk);
                bl[2 * nj][0] = r[0]; bl[2 * nj][1] = r[2];
                bl[2 * nj + 1][0] = r[1]; bl[2 * nj + 1][1] = r[3];
            }
#pragma unroll
            for (int mi = 0; mi < 4; mi++)
#pragma unroll
                for (int ni = 0; ni < 4; ni++) {
                    mma16816(acc[mi][ni], ah[mi], bh[ni]);
                    mma16816(acc[mi][ni], ah[mi], bl[ni]);
                }
            uint32_t al[4][4];
#pragma unroll
            for (int mi = 0; mi < 4; mi++)
                ldm4(al[mi], stg + MATB + (wm + mi * 16 + lrow) * AROWB + ksb + lchk);
#pragma unroll
            for (int mi = 0; mi < 4; mi++)
#pragma unroll
                for (int ni = 0; ni < 4; ni++)
                    mma16816(acc[mi][ni], al[mi], bh[ni]);
        }
    }

    // epilogue: C fragment -> global + bias (float2 stores)
    const int crow = lane >> 2;
    const int ccol = (lane & 3) * 2;
#pragma unroll
    for (int mi = 0; mi < 4; mi++) {
        int r0 = o0 + wm + mi * 16 + crow;
        float bv0 = g_bias[r0], bv8 = g_bias[r0 + 8];
        size_t rb0 = ((size_t)n * OC + r0) * 4096 + col0 + wn;
        size_t rb8 = rb0 + (size_t)8 * 4096;
#pragma unroll
        for (int ni = 0; ni < 4; ni++) {
            float2 v0 = make_float2(acc[mi][ni][0] + bv0, acc[mi][ni][1] + bv0);
            float2 v8 = make_float2(acc[mi][ni][2] + bv8, acc[mi][ni][3] + bv8);
            *(float2*)&g_qkv[rb0 + ni * 8 + ccol] = v0;
            *(float2*)&g_qkv[rb8 + ni * 8 + ccol] = v8;
        }
    }
}

// ---------------------------------------------- K1b: [h][w] -> [w][h] transpose
__global__ void __launch_bounds__(256) k_trans() {
    const int o = blockIdx.x, n = blockIdx.y;
    const float4* in4 = (const float4*)(g_qkv + ((size_t)n * OC + o) * 4096);
    float4* out4 = (float4*)(g_qkvT + ((size_t)n * OC + o) * 4096);
    __shared__ float sm[64 * 65];
    const int tid = threadIdx.x;
#pragma unroll
    for (int l = 0; l < 4; l++) {
        int u = tid + l * 256;
        int h = u >> 4, w0 = (u & 15) * 4;
        float4 v = in4[u];
        sm[h * 65 + w0 + 0] = v.x;
        sm[h * 65 + w0 + 1] = v.y;
        sm[h * 65 + w0 + 2] = v.z;
        sm[h * 65 + w0 + 3] = v.w;
    }
    __syncthreads();
#pragma unroll
    for (int l = 0; l < 4; l++) {
        int u = tid + l * 256;
        int w = u >> 4, h0 = (u & 15) * 4;
        float4 v = make_float4(sm[(h0 + 0) * 65 + w], sm[(h0 + 1) * 65 + w],
                               sm[(h0 + 2) * 65 + w], sm[(h0 + 3) * 65 + w]);
        out4[u] = v;
    }
}

// -------------------------------------------- K2+K3: relative-emb GEMMs (merged)
__global__ void __launch_bounds__(256) k_rel() {
    const int fi = blockIdx.x, gy = blockIdx.y, n = blockIdx.z;
    const int isK = gy >> 3, g = gy & 7;
    const int ch0 = isK ? 32 : 0;
    float* ob = isK ? g_simT : g_sim;
    const float s = g_s[(isK ? 16 : 8) + g];
    __shared__ __align__(16) float Qs[2048];
    __shared__ __align__(16) float Es[2048];
    const int tid = threadIdx.x;
    const int tx = tid & 15, ty = tid >> 4;

    const size_t qbase = ((size_t)n * OC + g * 128 + ch0) * 4096 + fi * 64;
    const int ebase = ch0 * 4096 + fi * 64;
#pragma unroll
    for (int l = 0; l < 8; l++) {
        int idx = tid + l * 256;
        int c = idx >> 6, u = idx & 63;
        Qs[idx] = g_qkv[qbase + (size_t)c * 4096 + u];
        Es[idx] = g_emb[ebase + c * 4096 + u];
    }
    __syncthreads();

    float2 acc[4][2];
#pragma unroll
    for (int ii = 0; ii < 4; ii++) { acc[ii][0] = make_float2(0.f, 0.f); acc[ii][1] = make_float2(0.f, 0.f); }
#pragma unroll
    for (int c = 0; c < 32; c++) {
        float4 e4 = *(const float4*)&Es[c * 64 + tx * 4];
        float2 e0 = make_float2(e4.x, e4.y), e1 = make_float2(e4.z, e4.w);
#pragma unroll
        for (int ii = 0; ii < 4; ii++) {
            float a = Qs[c * 64 + ty * 4 + ii];
            float2 ad = make_float2(a, a);
            acc[ii][0] = ffma2(ad, e0, acc[ii][0]);
            acc[ii][1] = ffma2(ad, e1, acc[ii][1]);
        }
    }
#pragma unroll
    for (int ii = 0; ii < 4; ii++) {
        int w = ty * 4 + ii;
        int b = n * 64 + w;
        float4 o4 = make_float4(acc[ii][0].x * s, acc[ii][0].y * s,
                                acc[ii][1].x * s, acc[ii][1].y * s);
        *(float4*)&ob[((size_t)b * 8 + g) * 4096 + fi * 64 + tx * 4] = o4;
    }
}

// ----------------------- K4: qk + compose + softmax + P@V ; stores P(fp16), sv(fp16)
__global__ void __launch_bounds__(256) k_attn() {
    const int w = blockIdx.x, g = blockIdx.y, n = blockIdx.z;
    const int b = n * 64 + w;
    __shared__ __align__(16) float smA[4160];
    __shared__ __align__(16) float smB[4160];
    const int tid = threadIdx.x;
    const int tx = tid & 15, ty = tid >> 4;
    const size_t qT = ((size_t)n * OC + g * 128) * 4096 + w * 64;
    const size_t simBase = ((size_t)b * 8 + g) * 4096;

#pragma unroll
    for (int l = 0; l < 8; l++) {
        int idx = tid + l * 256;
        int c = idx >> 6, u = idx & 63;
        smA[idx]        = g_qkvT[qT + (size_t)c * 4096 + u];
        smA[2048 + idx] = g_qkvT[qT + (size_t)(32 + c) * 4096 + u];
    }
#pragma unroll
    for (int l = 0; l < 16; l++) {
        int idx = tid + l * 256;
        int j = idx >> 6, u = idx & 63;
        smB[j * 65 + u] = g_simT[simBase + idx];
    }
    __syncthreads();

    float2 acc[4][2];
#pragma unroll
    for (int ii = 0; ii < 4; ii++) { acc[ii][0] = make_float2(0.f, 0.f); acc[ii][1] = make_float2(0.f, 0.f); }
#pragma unroll
    for (int c = 0; c < 32; c++) {
        float4 k4 = *(const float4*)&smA[2048 + c * 64 + tx * 4];
        float2 k0 = make_float2(k4.x, k4.y), k1 = make_float2(k4.z, k4.w);
#pragma unroll
        for (int ii = 0; ii < 4; ii++) {
            float a = smA[c * 64 + ty * 4 + ii];
            float2 ad = make_float2(a, a);
            acc[ii][0] = ffma2(ad, k0, acc[ii][0]);
            acc[ii][1] = ffma2(ad, k1, acc[ii][1]);
        }
    }

    const float sqk = g_s[g];
    float p[4][4];
#pragma unroll
    for (int ii = 0; ii < 4; ii++) {
        int i = ty * 4 + ii;
        float4 qr4 = *(const float4*)&g_sim[simBase + i * 64 + tx * 4];
        float l0 = sqk * acc[ii][0].x + qr4.x + smB[(tx * 4 + 0) * 65 + i];
        float l1 = sqk * acc[ii][0].y + qr4.y + smB[(tx * 4 + 1) * 65 + i];
        float l2 = sqk * acc[ii][1].x + qr4.z + smB[(tx * 4 + 2) * 65 + i];
        float l3 = sqk * acc[ii][1].y + qr4.w + smB[(tx * 4 + 3) * 65 + i];
        float m = fmaxf(fmaxf(l0, l1), fmaxf(l2, l3));
#pragma unroll
        for (int d = 1; d < 16; d <<= 1) m = fmaxf(m, __shfl_xor_sync(0xffffffffu, m, d));
        float e0 = __expf(l0 - m), e1 = __expf(l1 - m), e2 = __expf(l2 - m), e3 = __expf(l3 - m);
        float ssum = e0 + e1 + e2 + e3;
#pragma unroll
        for (int d = 1; d < 16; d <<= 1) ssum += __shfl_xor_sync(0xffffffffu, ssum, d);
        float inv = 1.0f / ssum;
        p[ii][0] = e0 * inv; p[ii][1] = e1 * inv; p[ii][2] = e2 * inv; p[ii][3] = e3 * inv;
    }
    __syncthreads();

#pragma unroll
    for (int ii = 0; ii < 4; ii++) {
        int i = ty * 4 + ii;
        smA[i * 65 + tx * 4 + 0] = p[ii][0];
        smA[i * 65 + tx * 4 + 1] = p[ii][1];
        smA[i * 65 + tx * 4 + 2] = p[ii][2];
        smA[i * 65 + tx * 4 + 3] = p[ii][3];
        uint2 pu = make_uint2(pack_h2(p[ii][0], p[ii][1]), pack_h2(p[ii][2], p[ii][3]));
        *(uint2*)&g_p[simBase + i * 64 + tx * 4] = pu;
    }
#pragma unroll
    for (int l = 0; l < 16; l++) {
        int idx = tid + l * 256;
        int c = idx >> 6, j = idx & 63;
        smB[c * 65 + j] = g_qkvT[qT + (size_t)(64 + c) * 4096 + j];
    }
    __syncthreads();

    float2 a2[4][2];
#pragma unroll
    for (int cc = 0; cc < 4; cc++) { a2[cc][0] = make_float2(0.f, 0.f); a2[cc][1] = make_float2(0.f, 0.f); }
#pragma unroll
    for (int j = 0; j < 64; j++) {
        float pr0 = smA[(tx * 4 + 0) * 65 + j];
        float pr1 = smA[(tx * 4 + 1) * 65 + j];
        float pr2 = smA[(tx * 4 + 2) * 65 + j];
        float pr3 = smA[(tx * 4 + 3) * 65 + j];
        float2 pp0 = make_float2(pr0, pr1), pp1 = make_float2(pr2, pr3);
#pragma unroll
        for (int cc = 0; cc < 4; cc++) {
            float v = smB[(ty * 4 + cc) * 65 + j];
            float2 vd = make_float2(v, v);
            a2[cc][0] = ffma2(vd, pp0, a2[cc][0]);
            a2[cc][1] = ffma2(vd, pp1, a2[cc][1]);
        }
    }
    // transpose (c,i) -> (i,c) through smB, then store sv[n][g][i][w*64+c] fp16
    __syncthreads();
#pragma unroll
    for (int cc = 0; cc < 4; cc++) {
        int c = ty * 4 + cc;
        smB[c * 65 + tx * 4 + 0] = a2[cc][0].x;
        smB[c * 65 + tx * 4 + 1] = a2[cc][0].y;
        smB[c * 65 + tx * 4 + 2] = a2[cc][1].x;
        smB[c * 65 + tx * 4 + 3] = a2[cc][1].y;
    }
    __syncthreads();
    const size_t svB = ((size_t)(n * 8 + g) * 64) * 4096 + w * 64;
#pragma unroll
    for (int ii = 0; ii < 4; ii++) {
        int i = ty * 4 + ii;
        float v0 = smB[(tx * 4 + 0) * 65 + i];
        float v1 = smB[(tx * 4 + 1) * 65 + i];
        float v2 = smB[(tx * 4 + 2) * 65 + i];
        float v3 = smB[(tx * 4 + 3) * 65 + i];
        uint2 hu = make_uint2(pack_h2(v0, v1), pack_h2(v2, v3));
        *(uint2*)&g_svh[svB + (size_t)i * 4096 + tx * 4] = hu;
    }
}

// --------- K5 (fused K6): sve + BN + pair-sum -> out[n][f][i][w]
__global__ void __launch_bounds__(256) k_sve_out(float* __restrict__ out) {
    const int i = blockIdx.x, g = blockIdx.y, n = blockIdx.z;
    __shared__ float Ps[4160];   // [w][j]
    __shared__ float Ves[4160];  // [c][j]
    __shared__ float Svs[4160];  // [w][c]
    const int tid = threadIdx.x;
    const int tx = tid & 15, ty = tid >> 4;
    const size_t svRow = ((size_t)(n * 8 + g) * 64 + i) * 4096;
    // Ves (fp32 from emb)
#pragma unroll
    for (int l = 0; l < 16; l++) {
        int idx = tid + l * 256;
        int r = idx >> 6, u = idx & 63;
        Ves[r * 65 + u] = g_emb[(64 + r) * 4096 + i * 64 + u];
    }
    // Ps (fp16), Svs (fp16) via half2 loads
#pragma unroll
    for (int l = 0; l < 8; l++) {
        int idx = tid + l * 256;          // 0..2047 half2 indices
        int r = idx >> 5, u2 = idx & 31;
        __half2 ph = *(const __half2*)&g_p[((size_t)(n * 64 + r) * 8 + g) * 4096 + i * 64 + u2 * 2];
        float2 pf = __half22float2(ph);
        Ps[r * 65 + u2 * 2 + 0] = pf.x;
        Ps[r * 65 + u2 * 2 + 1] = pf.y;
        __half2 sh = *(const __half2*)&g_svh[svRow + r * 64 + u2 * 2];
        float2 sf = __half22float2(sh);
        Svs[r * 65 + u2 * 2 + 0] = sf.x;
        Svs[r * 65 + u2 * 2 + 1] = sf.y;
    }
    __syncthreads();

    float2 a2[4][2];
#pragma unroll
    for (int cc = 0; cc < 4; cc++) { a2[cc][0] = make_float2(0.f, 0.f); a2[cc][1] = make_float2(0.f, 0.f); }
#pragma unroll
    for (int j = 0; j < 64; j++) {
        float pw0 = Ps[(tx * 4 + 0) * 65 + j];
        float pw1 = Ps[(tx * 4 + 1) * 65 + j];
        float pw2 = Ps[(tx * 4 + 2) * 65 + j];
        float pw3 = Ps[(tx * 4 + 3) * 65 + j];
        float2 pp0 = make_float2(pw0, pw1), pp1 = make_float2(pw2, pw3);
#pragma unroll
        for (int cc = 0; cc < 4; cc++) {
            float v = Ves[(ty * 4 + cc) * 65 + j];
            float2 vd = make_float2(v, v);
            a2[cc][0] = ffma2(vd, pp0, a2[cc][0]);
            a2[cc][1] = ffma2(vd, pp1, a2[cc][1]);
        }
    }
    const size_t outBase = ((size_t)n * 512 + g * 64) * 4096 + i * 64;
#pragma unroll
    for (int cc = 0; cc < 4; cc++) {
        int c = ty * 4 + cc;
        int f = g * 64 + c;
        float a0 = g_oa[2 * f], a1 = g_oa[2 * f + 1], bb = g_ob[f];
        float s0 = Svs[(tx * 4 + 0) * 65 + c];
        float s1 = Svs[(tx * 4 + 1) * 65 + c];
        float s2 = Svs[(tx * 4 + 2) * 65 + c];
        float s3 = Svs[(tx * 4 + 3) * 65 + c];
        float4 o4 = make_float4(a0 * s0 + a1 * a2[cc][0].x + bb,
                                a0 * s1 + a1 * a2[cc][0].y + bb,
                                a0 * s2 + a1 * a2[cc][1].x + bb,
                                a0 * s3 + a1 * a2[cc][1].y + bb);
        *(float4*)&out[outBase + (size_t)c * 4096 + tx * 4] = o4;
    }
}

// ---------------------------------------------------------------------------
extern "C" void kernel_launch(void* const* d_in, const int* in_sizes, int n_in,
                              void* d_out, int out_size) {
    const float* x     = (const float*)d_in[0];
    const float* w_qkv = (const float*)d_in[1];
    const float* rel   = (const float*)d_in[2];
    const float* bnq_g = (const float*)d_in[3];
    const float* bnq_b = (const float*)d_in[4];
    const float* bnq_m = (const float*)d_in[5];
    const float* bnq_v = (const float*)d_in[6];
    const float* bns_g = (const float*)d_in[7];
    const float* bns_v = (const float*)d_in[10];
    const float* bno_g = (const float*)d_in[11];
    const float* bno_b = (const float*)d_in[12];
    const float* bno_m = (const float*)d_in[13];
    const float* bno_v = (const float*)d_in[14];
    float* out = (float*)d_out;

    cudaFuncSetAttribute(k_gemm, cudaFuncAttributeMaxDynamicSharedMemorySize, SMEM_GEMM);

    k_conv_w<<<1024, 512>>>(w_qkv, bnq_g, bnq_b, bnq_m, bnq_v);
    k_prep_emb<<<dim3(128, 64), 64>>>(rel);
    k_prep_sc<<<1, 512>>>(bns_g, bns_v, bno_g, bno_b, bno_m, bno_v);
    k_conv_x<<<dim3(64, 8, 16), 256>>>(x);

    k_gemm<<<dim3(32, 8, 16), 256, SMEM_GEMM>>>();

    k_trans<<<dim3(1024, 16), 256>>>();
    k_rel<<<dim3(64, 16, 16), 256>>>();
    k_attn<<<dim3(64, 8, 16), 256>>>();
    k_sve_out<<<dim3(64, 8, 16), 256>>>(out);
}

// round 14
// speedup vs baseline: 1.6869x; 1.6869x over previous
#include <cuda_runtime.h>
#include <cuda_bf16.h>
#include <cuda_fp16.h>
#include <cstdint>

// ----------------------------------------------------------------------------
// AxialAttention (height axis). x(16,512,64,64), w_qkv(1024,512), relative(128,127)
// NW=1024 (b = n*64+w), G=8 heads, q/k: 32 ch, v: 64 ch per head.
// K1 (QKV 1x1-conv GEMM): bf16 hi/lo split on mma.sync (HMMA); tcgen05 is
// unavailable (harness targets compute_103, no 'a' feature set).
// This round: revert GEMM to 2-stage (2 CTAs/SM — the 4-stage ring halved
// occupancy and regressed 850us); keep fp16 P/sv tail.
// ----------------------------------------------------------------------------

#define CIN 512
#define OC  1024
#define BN_EPS 1e-5f

// ------------------------------ scratch (__device__ globals; no allocations)
__device__ float g_bias[OC];                 // folded conv bias
__device__ float g_emb[128 * 64 * 64];       // all_emb[ch][i][j] = rel[ch, i-j+63]
__device__ float g_s[24];                    // bns scales (qk: g, qr: 8+g, kr: 16+g)
__device__ float g_oa[1024];                 // bno scales per filter (sv, sve)
__device__ float g_ob[512];                  // bno combined bias per filter
__device__ __nv_bfloat16 g_w_hi[OC * CIN];   // folded conv weight, bf16 hi
__device__ __nv_bfloat16 g_w_lo[OC * CIN];   // bf16 lo residual
__device__ __nv_bfloat16 g_xt_hi[(size_t)16 * 4096 * 512]; // x^T [n*4096+hw][c] hi
__device__ __nv_bfloat16 g_xt_lo[(size_t)16 * 4096 * 512]; // lo
__device__ float g_qkv[(size_t)16 * 1024 * 4096];   // [n][o][h*64+w]
__device__ float g_qkvT[(size_t)16 * 1024 * 4096];  // [n][o][w*64+h]
__device__ float g_sim[(size_t)1024 * 8 * 4096];    // [b][g][i][j]: qr
__device__ float g_simT[(size_t)1024 * 8 * 4096];   // [b][g][j][i]: kr
__device__ __half g_p[(size_t)1024 * 8 * 4096];     // [b][g][i][j]: softmax P (fp16)
__device__ __half g_svh[(size_t)16 * 8 * 64 * 4096];// [n][g][i][w*64+c] sv (fp16)

// ------------------------------------------------------------- PTX helpers
__device__ __forceinline__ float2 ffma2(float2 a, float2 b, float2 c) {
    float2 d;
    asm("{\n\t"
        ".reg .b64 ra, rb, rc;\n\t"
        "mov.b64 ra, {%2, %3};\n\t"
        "mov.b64 rb, {%4, %5};\n\t"
        "mov.b64 rc, {%6, %7};\n\t"
        "fma.rn.f32x2 rc, ra, rb, rc;\n\t"
        "mov.b64 {%0, %1}, rc;\n\t"
        "}"
        : "=f"(d.x), "=f"(d.y)
        : "f"(a.x), "f"(a.y), "f"(b.x), "f"(b.y), "f"(c.x), "f"(c.y));
    return d;
}

__device__ __forceinline__ uint32_t s2u(const void* p) {
    uint32_t a;
    asm("{ .reg .u64 t; cvta.to.shared.u64 t, %1; cvt.u32.u64 %0, t; }" : "=r"(a) : "l"(p));
    return a;
}
__device__ __forceinline__ void cp16(uint32_t s, const void* g) {
    asm volatile("cp.async.cg.shared.global [%0], [%1], 16;" :: "r"(s), "l"(g));
}
#define CP_COMMIT() asm volatile("cp.async.commit_group;" ::: "memory")
#define CP_WAIT(n)  asm volatile("cp.async.wait_group %0;" :: "n"(n) : "memory")

__device__ __forceinline__ void ldm4(uint32_t* r, uint32_t addr) {
    asm volatile("ldmatrix.sync.aligned.m8n8.x4.shared.b16 {%0,%1,%2,%3}, [%4];"
                 : "=r"(r[0]), "=r"(r[1]), "=r"(r[2]), "=r"(r[3]) : "r"(addr));
}
__device__ __forceinline__ void mma16816(float* c, const uint32_t* a, const uint32_t* b) {
    asm volatile(
        "mma.sync.aligned.m16n8k16.row.col.f32.bf16.bf16.f32 "
        "{%0,%1,%2,%3}, {%4,%5,%6,%7}, {%8,%9}, {%0,%1,%2,%3};"
        : "+f"(c[0]), "+f"(c[1]), "+f"(c[2]), "+f"(c[3])
        : "r"(a[0]), "r"(a[1]), "r"(a[2]), "r"(a[3]), "r"(b[0]), "r"(b[1]));
}

__device__ __forceinline__ uint32_t pack_h2(float a, float b) {
    __half2 h = __floats2half2_rn(a, b);
    return *(uint32_t*)&h;
}

// -------------------------------------------------------------- prep kernels
__global__ void k_conv_w(const float* __restrict__ w,
                         const float* __restrict__ gg, const float* __restrict__ gb,
                         const float* __restrict__ gm, const float* __restrict__ gv) {
    int o = blockIdx.x, c = threadIdx.x;
    float sc = gg[o] * rsqrtf(gv[o] + BN_EPS);
    float v = w[o * CIN + c] * sc;
    __nv_bfloat16 h = __float2bfloat16(v);
    g_w_hi[o * CIN + c] = h;
    g_w_lo[o * CIN + c] = __float2bfloat16(v - __bfloat162float(h));
    if (c == 0) g_bias[o] = gb[o] - gm[o] * sc;
}

__global__ void k_prep_emb(const float* __restrict__ rel) {
    int ch = blockIdx.x, i = blockIdx.y, j = threadIdx.x;
    g_emb[(ch * 64 + i) * 64 + j] = rel[ch * 127 + (i - j + 63)];
}

__global__ void k_prep_sc(const float* __restrict__ sg, const float* __restrict__ svv,
                          const float* __restrict__ og, const float* __restrict__ ob_,
                          const float* __restrict__ om, const float* __restrict__ ov) {
    int t = threadIdx.x;  // 512
    if (t < 24) g_s[t] = sg[t] * rsqrtf(svv[t] + BN_EPS);
    float a0 = og[2 * t] * rsqrtf(ov[2 * t] + BN_EPS);
    float a1 = og[2 * t + 1] * rsqrtf(ov[2 * t + 1] + BN_EPS);
    g_oa[2 * t] = a0;
    g_oa[2 * t + 1] = a1;
    g_ob[t] = (ob_[2 * t] - om[2 * t] * a0) + (ob_[2 * t + 1] - om[2 * t + 1] * a1);
}

// x [n][c][hw] fp32 -> x^T [n*4096+hw][c] bf16 hi/lo (K-contiguous B for mma)
__global__ void __launch_bounds__(256) k_conv_x(const float* __restrict__ x) {
    const int hw0 = blockIdx.x * 64, c0 = blockIdx.y * 64, n = blockIdx.z;
    __shared__ float sm[64 * 65];
    const int tid = threadIdx.x;
    const float* src = x + ((size_t)n * CIN + c0) * 4096 + hw0;
#pragma unroll
    for (int l = 0; l < 16; l++) {
        int idx = tid + l * 256;
        int r = idx >> 6, u = idx & 63;  // r = c-local, u = hw-local
        sm[r * 65 + u] = src[(size_t)r * 4096 + u];
    }
    __syncthreads();
    __nv_bfloat16* dh = g_xt_hi + ((size_t)n * 4096 + hw0) * CIN + c0;
    __nv_bfloat16* dl = g_xt_lo + ((size_t)n * 4096 + hw0) * CIN + c0;
#pragma unroll
    for (int l = 0; l < 16; l++) {
        int idx = tid + l * 256;
        int r = idx >> 6, u = idx & 63;  // r = hw-local, u = c-local
        float v = sm[u * 65 + r];
        __nv_bfloat16 h = __float2bfloat16(v);
        dh[(size_t)r * CIN + u] = h;
        dl[(size_t)r * CIN + u] = __float2bfloat16(v - __bfloat162float(h));
    }
}

// ------------------------------------------ K1: bf16-split mma.sync GEMM
// per n: qkv[o0+128, col0+128] = W(1024x512) @ X(512x4096) + bias
// CTA 128x128, BK=32, 2-stage cp.async (81920B smem -> 2 CTAs/SM).
// Warp tile 64x32 (2x4 warp grid). SMEM row stride 80B (conflict-free ldmatrix).
#define AROWB   80
#define MATB    (128 * AROWB)     // 10240 per matrix
#define STAGEB  (4 * MATB)        // A_hi, A_lo, B_hi, B_lo
#define SMEM_GEMM (2 * STAGEB)    // 81920

__device__ __forceinline__ void gemm_loads(int tid, int o0, size_t nb, int k0, uint32_t s) {
#pragma unroll
    for (int l = 0; l < 2; l++) {
        int idx = tid + l * 256;           // 0..511
        int r = idx >> 2, t = idx & 3;     // row, 16B chunk
        uint32_t so = r * AROWB + t * 16;
        size_t ga = (size_t)(o0 + r) * CIN + k0 + t * 8;
        cp16(s + so, g_w_hi + ga);
        cp16(s + MATB + so, g_w_lo + ga);
        size_t gb = (nb + r) * CIN + k0 + t * 8;
        cp16(s + 2 * MATB + so, g_xt_hi + gb);
        cp16(s + 3 * MATB + so, g_xt_lo + gb);
    }
}

__global__ void __launch_bounds__(256) k_gemm() {
    extern __shared__ __align__(128) char smem[];
    const uint32_t sb = s2u(smem);
    const int tid = threadIdx.x, wid = tid >> 5, lane = tid & 31;
    const int col0 = blockIdx.x * 128;
    const int o0 = blockIdx.y * 128;
    const int n = blockIdx.z;
    const size_t nb = (size_t)n * 4096 + col0;
    const uint32_t st0 = sb, st1 = sb + STAGEB;
    const int wm = (wid >> 2) * 64, wn = (wid & 3) * 32;

    float acc[4][4][4];
#pragma unroll
    for (int mi = 0; mi < 4; mi++)
#pragma unroll
        for (int ni = 0; ni < 4; ni++)
#pragma unroll
            for (int e = 0; e < 4; e++) acc[mi][ni][e] = 0.f;

    gemm_loads(tid, o0, nb, 0, st0);
    CP_COMMIT();
    gemm_loads(tid, o0, nb, 32, st1);
    CP_COMMIT();

    const int lrow = lane & 15;
    const int lchk = (lane >> 4) * 16;

    for (int c = 0; c < 16; c++) {
        const uint32_t stg = (c & 1) ? st1 : st0;
        if (c < 15) CP_WAIT(1); else CP_WAIT(0);
        __syncthreads();
#pragma unroll
        for (int ks = 0; ks < 2; ks++) {
            const int ksb = ks * 32;
            uint32_t ah[4][4], bh[4][2], bl[4][2];
#pragma unroll
            for (int mi = 0; mi < 4; mi++)
                ldm4(ah[mi], stg + (wm + mi * 16 + lrow) * AROWB + ksb + lchk);
#pragma unroll
            for (int nj = 0; nj < 2; nj++) {
                uint32_t r[4];
                ldm4(r, stg + 2 * MATB + (wn + nj * 16 + lrow) * AROWB + ksb + lchk);
                bh[2 * nj][0] = r[0]; bh[2 * nj][1] = r[2];
                bh[2 * nj + 1][0] = r[1]; bh[2 * nj + 1][1] = r[3];
                ldm4(r, stg + 3 * MATB + (wn + nj * 16 + lrow) * AROWB + ksb + lchk);
                bl[2 * nj][0] = r[0]; bl[2 * nj][1] = r[2];
                bl[2 * nj + 1][0] = r[1]; bl[2 * nj + 1][1] = r[3];
            }
#pragma unroll
            for (int mi = 0; mi < 4; mi++)
#pragma unroll
                for (int ni = 0; ni < 4; ni++) {
                    mma16816(acc[mi][ni], ah[mi], bh[ni]);
                    mma16816(acc[mi][ni], ah[mi], bl[ni]);
                }
            uint32_t al[4][4];
#pragma unroll
            for (int mi = 0; mi < 4; mi++)
                ldm4(al[mi], stg + MATB + (wm + mi * 16 + lrow) * AROWB + ksb + lchk);
#pragma unroll
            for (int mi = 0; mi < 4; mi++)
#pragma unroll
                for (int ni = 0; ni < 4; ni++)
                    mma16816(acc[mi][ni], al[mi], bh[ni]);
        }
        __syncthreads();
        if (c < 14) {
            gemm_loads(tid, o0, nb, (c + 2) * 32, stg);
            CP_COMMIT();
        }
    }

    // epilogue: C fragment -> global + bias (float2 stores)
    const int crow = lane >> 2;
    const int ccol = (lane & 3) * 2;
#pragma unroll
    for (int mi = 0; mi < 4; mi++) {
        int r0 = o0 + wm + mi * 16 + crow;
        float bv0 = g_bias[r0], bv8 = g_bias[r0 + 8];
        size_t rb0 = ((size_t)n * OC + r0) * 4096 + col0 + wn;
        size_t rb8 = rb0 + (size_t)8 * 4096;
#pragma unroll
        for (int ni = 0; ni < 4; ni++) {
            float2 v0 = make_float2(acc[mi][ni][0] + bv0, acc[mi][ni][1] + bv0);
            float2 v8 = make_float2(acc[mi][ni][2] + bv8, acc[mi][ni][3] + bv8);
            *(float2*)&g_qkv[rb0 + ni * 8 + ccol] = v0;
            *(float2*)&g_qkv[rb8 + ni * 8 + ccol] = v8;
        }
    }
}

// ---------------------------------------------- K1b: [h][w] -> [w][h] transpose
__global__ void __launch_bounds__(256) k_trans() {
    const int o = blockIdx.x, n = blockIdx.y;
    const float4* in4 = (const float4*)(g_qkv + ((size_t)n * OC + o) * 4096);
    float4* out4 = (float4*)(g_qkvT + ((size_t)n * OC + o) * 4096);
    __shared__ float sm[64 * 65];
    const int tid = threadIdx.x;
#pragma unroll
    for (int l = 0; l < 4; l++) {
        int u = tid + l * 256;
        int h = u >> 4, w0 = (u & 15) * 4;
        float4 v = in4[u];
        sm[h * 65 + w0 + 0] = v.x;
        sm[h * 65 + w0 + 1] = v.y;
        sm[h * 65 + w0 + 2] = v.z;
        sm[h * 65 + w0 + 3] = v.w;
    }
    __syncthreads();
#pragma unroll
    for (int l = 0; l < 4; l++) {
        int u = tid + l * 256;
        int w = u >> 4, h0 = (u & 15) * 4;
        float4 v = make_float4(sm[(h0 + 0) * 65 + w], sm[(h0 + 1) * 65 + w],
                               sm[(h0 + 2) * 65 + w], sm[(h0 + 3) * 65 + w]);
        out4[u] = v;
    }
}

// -------------------------------------------- K2+K3: relative-emb GEMMs (merged)
__global__ void __launch_bounds__(256) k_rel() {
    const int fi = blockIdx.x, gy = blockIdx.y, n = blockIdx.z;
    const int isK = gy >> 3, g = gy & 7;
    const int ch0 = isK ? 32 : 0;
    float* ob = isK ? g_simT : g_sim;
    const float s = g_s[(isK ? 16 : 8) + g];
    __shared__ __align__(16) float Qs[2048];
    __shared__ __align__(16) float Es[2048];
    const int tid = threadIdx.x;
    const int tx = tid & 15, ty = tid >> 4;

    const size_t qbase = ((size_t)n * OC + g * 128 + ch0) * 4096 + fi * 64;
    const int ebase = ch0 * 4096 + fi * 64;
#pragma unroll
    for (int l = 0; l < 8; l++) {
        int idx = tid + l * 256;
        int c = idx >> 6, u = idx & 63;
        Qs[idx] = g_qkv[qbase + (size_t)c * 4096 + u];
        Es[idx] = g_emb[ebase + c * 4096 + u];
    }
    __syncthreads();

    float2 acc[4][2];
#pragma unroll
    for (int ii = 0; ii < 4; ii++) { acc[ii][0] = make_float2(0.f, 0.f); acc[ii][1] = make_float2(0.f, 0.f); }
#pragma unroll
    for (int c = 0; c < 32; c++) {
        float4 e4 = *(const float4*)&Es[c * 64 + tx * 4];
        float2 e0 = make_float2(e4.x, e4.y), e1 = make_float2(e4.z, e4.w);
#pragma unroll
        for (int ii = 0; ii < 4; ii++) {
            float a = Qs[c * 64 + ty * 4 + ii];
            float2 ad = make_float2(a, a);
            acc[ii][0] = ffma2(ad, e0, acc[ii][0]);
            acc[ii][1] = ffma2(ad, e1, acc[ii][1]);
        }
    }
#pragma unroll
    for (int ii = 0; ii < 4; ii++) {
        int w = ty * 4 + ii;
        int b = n * 64 + w;
        float4 o4 = make_float4(acc[ii][0].x * s, acc[ii][0].y * s,
                                acc[ii][1].x * s, acc[ii][1].y * s);
        *(float4*)&ob[((size_t)b * 8 + g) * 4096 + fi * 64 + tx * 4] = o4;
    }
}

// ----------------------- K4: qk + compose + softmax + P@V ; stores P(fp16), sv(fp16)
__global__ void __launch_bounds__(256) k_attn() {
    const int w = blockIdx.x, g = blockIdx.y, n = blockIdx.z;
    const int b = n * 64 + w;
    __shared__ __align__(16) float smA[4160];
    __shared__ __align__(16) float smB[4160];
    const int tid = threadIdx.x;
    const int tx = tid & 15, ty = tid >> 4;
    const size_t qT = ((size_t)n * OC + g * 128) * 4096 + w * 64;
    const size_t simBase = ((size_t)b * 8 + g) * 4096;

#pragma unroll
    for (int l = 0; l < 8; l++) {
        int idx = tid + l * 256;
        int c = idx >> 6, u = idx & 63;
        smA[idx]        = g_qkvT[qT + (size_t)c * 4096 + u];
        smA[2048 + idx] = g_qkvT[qT + (size_t)(32 + c) * 4096 + u];
    }
#pragma unroll
    for (int l = 0; l < 16; l++) {
        int idx = tid + l * 256;
        int j = idx >> 6, u = idx & 63;
        smB[j * 65 + u] = g_simT[simBase + idx];
    }
    __syncthreads();

    float2 acc[4][2];
#pragma unroll
    for (int ii = 0; ii < 4; ii++) { acc[ii][0] = make_float2(0.f, 0.f); acc[ii][1] = make_float2(0.f, 0.f); }
#pragma unroll
    for (int c = 0; c < 32; c++) {
        float4 k4 = *(const float4*)&smA[2048 + c * 64 + tx * 4];
        float2 k0 = make_float2(k4.x, k4.y), k1 = make_float2(k4.z, k4.w);
#pragma unroll
        for (int ii = 0; ii < 4; ii++) {
            float a = smA[c * 64 + ty * 4 + ii];
            float2 ad = make_float2(a, a);
            acc[ii][0] = ffma2(ad, k0, acc[ii][0]);
            acc[ii][1] = ffma2(ad, k1, acc[ii][1]);
        }
    }

    const float sqk = g_s[g];
    float p[4][4];
#pragma unroll
    for (int ii = 0; ii < 4; ii++) {
        int i = ty * 4 + ii;
        float4 qr4 = *(const float4*)&g_sim[simBase + i * 64 + tx * 4];
        float l0 = sqk * acc[ii][0].x + qr4.x + smB[(tx * 4 + 0) * 65 + i];
        float l1 = sqk * acc[ii][0].y + qr4.y + smB[(tx * 4 + 1) * 65 + i];
        float l2 = sqk * acc[ii][1].x + qr4.z + smB[(tx * 4 + 2) * 65 + i];
        float l3 = sqk * acc[ii][1].y + qr4.w + smB[(tx * 4 + 3) * 65 + i];
        float m = fmaxf(fmaxf(l0, l1), fmaxf(l2, l3));
#pragma unroll
        for (int d = 1; d < 16; d <<= 1) m = fmaxf(m, __shfl_xor_sync(0xffffffffu, m, d));
        float e0 = __expf(l0 - m), e1 = __expf(l1 - m), e2 = __expf(l2 - m), e3 = __expf(l3 - m);
        float ssum = e0 + e1 + e2 + e3;
#pragma unroll
        for (int d = 1; d < 16; d <<= 1) ssum += __shfl_xor_sync(0xffffffffu, ssum, d);
        float inv = 1.0f / ssum;
        p[ii][0] = e0 * inv; p[ii][1] = e1 * inv; p[ii][2] = e2 * inv; p[ii][3] = e3 * inv;
    }
    __syncthreads();

#pragma unroll
    for (int ii = 0; ii < 4; ii++) {
        int i = ty * 4 + ii;
        smA[i * 65 + tx * 4 + 0] = p[ii][0];
        smA[i * 65 + tx * 4 + 1] = p[ii][1];
        smA[i * 65 + tx * 4 + 2] = p[ii][2];
        smA[i * 65 + tx * 4 + 3] = p[ii][3];
        uint2 pu = make_uint2(pack_h2(p[ii][0], p[ii][1]), pack_h2(p[ii][2], p[ii][3]));
        *(uint2*)&g_p[simBase + i * 64 + tx * 4] = pu;
    }
#pragma unroll
    for (int l = 0; l < 16; l++) {
        int idx = tid + l * 256;
        int c = idx >> 6, j = idx & 63;
        smB[c * 65 + j] = g_qkvT[qT + (size_t)(64 + c) * 4096 + j];
    }
    __syncthreads();

    float2 a2[4][2];
#pragma unroll
    for (int cc = 0; cc < 4; cc++) { a2[cc][0] = make_float2(0.f, 0.f); a2[cc][1] = make_float2(0.f, 0.f); }
#pragma unroll
    for (int j = 0; j < 64; j++) {
        float pr0 = smA[(tx * 4 + 0) * 65 + j];
        float pr1 = smA[(tx * 4 + 1) * 65 + j];
        float pr2 = smA[(tx * 4 + 2) * 65 + j];
        float pr3 = smA[(tx * 4 + 3) * 65 + j];
        float2 pp0 = make_float2(pr0, pr1), pp1 = make_float2(pr2, pr3);
#pragma unroll
        for (int cc = 0; cc < 4; cc++) {
            float v = smB[(ty * 4 + cc) * 65 + j];
            float2 vd = make_float2(v, v);
            a2[cc][0] = ffma2(vd, pp0, a2[cc][0]);
            a2[cc][1] = ffma2(vd, pp1, a2[cc][1]);
        }
    }
    // transpose (c,i) -> (i,c) through smB, then store sv[n][g][i][w*64+c] fp16
    __syncthreads();
#pragma unroll
    for (int cc = 0; cc < 4; cc++) {
        int c = ty * 4 + cc;
        smB[c * 65 + tx * 4 + 0] = a2[cc][0].x;
        smB[c * 65 + tx * 4 + 1] = a2[cc][0].y;
        smB[c * 65 + tx * 4 + 2] = a2[cc][1].x;
        smB[c * 65 + tx * 4 + 3] = a2[cc][1].y;
    }
    __syncthreads();
    const size_t svB = ((size_t)(n * 8 + g) * 64) * 4096 + w * 64;
#pragma unroll
    for (int ii = 0; ii < 4; ii++) {
        int i = ty * 4 + ii;
        float v0 = smB[(tx * 4 + 0) * 65 + i];
        float v1 = smB[(tx * 4 + 1) * 65 + i];
        float v2 = smB[(tx * 4 + 2) * 65 + i];
        float v3 = smB[(tx * 4 + 3) * 65 + i];
        uint2 hu = make_uint2(pack_h2(v0, v1), pack_h2(v2, v3));
        *(uint2*)&g_svh[svB + (size_t)i * 4096 + tx * 4] = hu;
    }
}

// --------- K5 (fused K6): sve + BN + pair-sum -> out[n][f][i][w]
__global__ void __launch_bounds__(256) k_sve_out(float* __restrict__ out) {
    const int i = blockIdx.x, g = blockIdx.y, n = blockIdx.z;
    __shared__ float Ps[4160];   // [w][j]
    __shared__ float Ves[4160];  // [c][j]
    __shared__ float Svs[4160];  // [w][c]
    const int tid = threadIdx.x;
    const int tx = tid & 15, ty = tid >> 4;
    const size_t svRow = ((size_t)(n * 8 + g) * 64 + i) * 4096;
#pragma unroll
    for (int l = 0; l < 16; l++) {
        int idx = tid + l * 256;
        int r = idx >> 6, u = idx & 63;
        Ves[r * 65 + u] = g_emb[(64 + r) * 4096 + i * 64 + u];
    }
#pragma unroll
    for (int l = 0; l < 8; l++) {
        int idx = tid + l * 256;          // 0..2047 half2 indices
        int r = idx >> 5, u2 = idx & 31;
        __half2 ph = *(const __half2*)&g_p[((size_t)(n * 64 + r) * 8 + g) * 4096 + i * 64 + u2 * 2];
        float2 pf = __half22float2(ph);
        Ps[r * 65 + u2 * 2 + 0] = pf.x;
        Ps[r * 65 + u2 * 2 + 1] = pf.y;
        __half2 sh = *(const __half2*)&g_svh[svRow + r * 64 + u2 * 2];
        float2 sf = __half22float2(sh);
        Svs[r * 65 + u2 * 2 + 0] = sf.x;
        Svs[r * 65 + u2 * 2 + 1] = sf.y;
    }
    __syncthreads();

    float2 a2[4][2];
#pragma unroll
    for (int cc = 0; cc < 4; cc++) { a2[cc][0] = make_float2(0.f, 0.f); a2[cc][1] = make_float2(0.f, 0.f); }
#pragma unroll
    for (int j = 0; j < 64; j++) {
        float pw0 = Ps[(tx * 4 + 0) * 65 + j];
        float pw1 = Ps[(tx * 4 + 1) * 65 + j];
        float pw2 = Ps[(tx * 4 + 2) * 65 + j];
        float pw3 = Ps[(tx * 4 + 3) * 65 + j];
        float2 pp0 = make_float2(pw0, pw1), pp1 = make_float2(pw2, pw3);
#pragma unroll
        for (int cc = 0; cc < 4; cc++) {
            float v = Ves[(ty * 4 + cc) * 65 + j];
            float2 vd = make_float2(v, v);
            a2[cc][0] = ffma2(vd, pp0, a2[cc][0]);
            a2[cc][1] = ffma2(vd, pp1, a2[cc][1]);
        }
    }
    const size_t outBase = ((size_t)n * 512 + g * 64) * 4096 + i * 64;
#pragma unroll
    for (int cc = 0; cc < 4; cc++) {
        int c = ty * 4 + cc;
        int f = g * 64 + c;
        float a0 = g_oa[2 * f], a1 = g_oa[2 * f + 1], bb = g_ob[f];
        float s0 = Svs[(tx * 4 + 0) * 65 + c];
        float s1 = Svs[(tx * 4 + 1) * 65 + c];
        float s2 = Svs[(tx * 4 + 2) * 65 + c];
        float s3 = Svs[(tx * 4 + 3) * 65 + c];
        float4 o4 = make_float4(a0 * s0 + a1 * a2[cc][0].x + bb,
                                a0 * s1 + a1 * a2[cc][0].y + bb,
                                a0 * s2 + a1 * a2[cc][1].x + bb,
                                a0 * s3 + a1 * a2[cc][1].y + bb);
        *(float4*)&out[outBase + (size_t)c * 4096 + tx * 4] = o4;
    }
}

// ---------------------------------------------------------------------------
extern "C" void kernel_launch(void* const* d_in, const int* in_sizes, int n_in,
                              void* d_out, int out_size) {
    const float* x     = (const float*)d_in[0];
    const float* w_qkv = (const float*)d_in[1];
    const float* rel   = (const float*)d_in[2];
    const float* bnq_g = (const float*)d_in[3];
    const float* bnq_b = (const float*)d_in[4];
    const float* bnq_m = (const float*)d_in[5];
    const float* bnq_v = (const float*)d_in[6];
    const float* bns_g = (const float*)d_in[7];
    const float* bns_v = (const float*)d_in[10];
    const float* bno_g = (const float*)d_in[11];
    const float* bno_b = (const float*)d_in[12];
    const float* bno_m = (const float*)d_in[13];
    const float* bno_v = (const float*)d_in[14];
    float* out = (float*)d_out;

    cudaFuncSetAttribute(k_gemm, cudaFuncAttributeMaxDynamicSharedMemorySize, SMEM_GEMM);

    k_conv_w<<<1024, 512>>>(w_qkv, bnq_g, bnq_b, bnq_m, bnq_v);
    k_prep_emb<<<dim3(128, 64), 64>>>(rel);
    k_prep_sc<<<1, 512>>>(bns_g, bns_v, bno_g, bno_b, bno_m, bno_v);
    k_conv_x<<<dim3(64, 8, 16), 256>>>(x);

    k_gemm<<<dim3(32, 8, 16), 256, SMEM_GEMM>>>();

    k_trans<<<dim3(1024, 16), 256>>>();
    k_rel<<<dim3(64, 16, 16), 256>>>();
    k_attn<<<dim3(64, 8, 16), 256>>>();
    k_sve_out<<<dim3(64, 8, 16), 256>>>(out);
}